// round 2
// baseline (speedup 1.0000x reference)
#include <cuda_runtime.h>
#include <cuda_bf16.h>
#include <math.h>

// Problem constants
#define BATCH 4
#define SEQ   2048
#define HEADS 16
#define DK    64
#define DMODEL 1024
#define MROWS (BATCH * SEQ)   // 8192

// ---------------- scratch (device globals; no allocation allowed) ----------
__device__ float g_q[BATCH * HEADS * SEQ * DK];   // [b,h,t,dk]
__device__ float g_k[BATCH * HEADS * SEQ * DK];
__device__ float g_v[BATCH * HEADS * SEQ * DK];
__device__ float g_ctx[MROWS * DMODEL];           // [b,t,d] attention output

// ---------------- GEMM: Out = X @ W^T + bias --------------------------------
// X: [M, 1024] row-major, W: [N, 1024] row-major (so W^T applied), both K-major.
// sel 0/1/2 -> write head-split into g_q/g_k/g_v ; sel 3 -> X := g_ctx, write plain OutPlain.
#define GBM 128
#define GBN 64
#define GBK 16

__global__ __launch_bounds__(256) void gemm_xwt(
    const float* __restrict__ Xin,
    const float* __restrict__ W,
    const float* __restrict__ bias,
    float* __restrict__ OutPlain,
    int sel)
{
    __shared__ float As[GBK][GBM];   // 8 KB
    __shared__ float Bs[GBK][GBN];   // 4 KB

    const float* X = (sel == 3) ? g_ctx : Xin;
    float* outHS = (sel == 0) ? g_q : (sel == 1) ? g_k : (sel == 2) ? g_v : nullptr;

    const int m0 = blockIdx.x * GBM;
    const int n0 = blockIdx.y * GBN;
    const int tid = threadIdx.x;
    const int ty = tid >> 4;        // 0..15
    const int tx = tid & 15;        // 0..15

    float acc[8][4];
#pragma unroll
    for (int i = 0; i < 8; i++)
#pragma unroll
        for (int j = 0; j < 4; j++) acc[i][j] = 0.f;

    for (int kb = 0; kb < DMODEL; kb += GBK) {
        // load A tile: 128 rows x 16 k  = 512 float4, 2 per thread
#pragma unroll
        for (int r = 0; r < 2; r++) {
            int id = tid + r * 256;
            int row = id >> 2;
            int k4 = id & 3;
            float4 v = *(const float4*)(X + (size_t)(m0 + row) * DMODEL + kb + k4 * 4);
            As[k4 * 4 + 0][row] = v.x;
            As[k4 * 4 + 1][row] = v.y;
            As[k4 * 4 + 2][row] = v.z;
            As[k4 * 4 + 3][row] = v.w;
        }
        // load B tile: 64 rows x 16 k = 256 float4, 1 per thread
        {
            int row = tid >> 2;
            int k4 = tid & 3;
            float4 v = *(const float4*)(W + (size_t)(n0 + row) * DMODEL + kb + k4 * 4);
            Bs[k4 * 4 + 0][row] = v.x;
            Bs[k4 * 4 + 1][row] = v.y;
            Bs[k4 * 4 + 2][row] = v.z;
            Bs[k4 * 4 + 3][row] = v.w;
        }
        __syncthreads();

#pragma unroll
        for (int kk = 0; kk < GBK; kk++) {
            float4 a0 = *(float4*)&As[kk][ty * 8];
            float4 a1 = *(float4*)&As[kk][ty * 8 + 4];
            float4 bv = *(float4*)&Bs[kk][tx * 4];
            float a[8] = {a0.x, a0.y, a0.z, a0.w, a1.x, a1.y, a1.z, a1.w};
            float b[4] = {bv.x, bv.y, bv.z, bv.w};
#pragma unroll
            for (int i = 0; i < 8; i++)
#pragma unroll
                for (int j = 0; j < 4; j++) acc[i][j] = fmaf(a[i], b[j], acc[i][j]);
        }
        __syncthreads();
    }

    // epilogue
    const int ncol = n0 + tx * 4;
    float4 bv4 = *(const float4*)(bias + ncol);
    if (sel < 3) {
        const int h = ncol >> 6;          // 4 | 64, so the float4 stays in one head
        const int dkb = ncol & 63;
#pragma unroll
        for (int i = 0; i < 8; i++) {
            int m = m0 + ty * 8 + i;
            int b = m >> 11;              // SEQ = 2048
            int t = m & (SEQ - 1);
            float4 o = make_float4(acc[i][0] + bv4.x, acc[i][1] + bv4.y,
                                   acc[i][2] + bv4.z, acc[i][3] + bv4.w);
            size_t dst = (((size_t)b * HEADS + h) * SEQ + t) * DK + dkb;
            *(float4*)&outHS[dst] = o;
        }
    } else {
#pragma unroll
        for (int i = 0; i < 8; i++) {
            int m = m0 + ty * 8 + i;
            float4 o = make_float4(acc[i][0] + bv4.x, acc[i][1] + bv4.y,
                                   acc[i][2] + bv4.z, acc[i][3] + bv4.w);
            *(float4*)&OutPlain[(size_t)m * DMODEL + ncol] = o;
        }
    }
}

// ---------------- Flash attention (causal, fp32 online softmax) -------------
// grid: (SEQ/64, BATCH*HEADS), block 256 threads (16x16), 4x4 per-thread tile.
#define TSTRIDE 68   // 64 + 4 pad, keeps float4 alignment

__global__ __launch_bounds__(256) void flash_attn()
{
    extern __shared__ float sm[];
    float* Qs = sm;                    // 64 x 68
    float* Ks = sm + 64 * TSTRIDE;
    float* Vs = sm + 2 * 64 * TSTRIDE;
    float* Ps = sm + 3 * 64 * TSTRIDE;

    const int qi = blockIdx.x;
    const int bh = blockIdx.y;
    const int q0 = qi * 64;
    const int tid = threadIdx.x;
    const int ty = tid >> 4, tx = tid & 15;
    const int ty4 = ty * 4, tx4 = tx * 4;

    // load Q tile
    const float* qbase = g_q + ((size_t)bh * SEQ + q0) * DK;
    for (int it = tid; it < 64 * 16; it += 256) {
        int row = it >> 4, c4 = it & 15;
        *(float4*)&Qs[row * TSTRIDE + c4 * 4] = *(const float4*)(qbase + row * DK + c4 * 4);
    }

    float m_i[4], l_i[4], acc[4][4];
#pragma unroll
    for (int i = 0; i < 4; i++) {
        m_i[i] = -3.0e38f;
        l_i[i] = 0.f;
#pragma unroll
        for (int j = 0; j < 4; j++) acc[i][j] = 0.f;
    }

    const float* kbase = g_k + (size_t)bh * SEQ * DK;
    const float* vbase = g_v + (size_t)bh * SEQ * DK;

    for (int jt = 0; jt <= qi; jt++) {
        const int j0 = jt * 64;
        __syncthreads();   // prior iteration done with Ks/Vs/Ps
        for (int it = tid; it < 64 * 16; it += 256) {
            int row = it >> 4, c4 = it & 15;
            *(float4*)&Ks[row * TSTRIDE + c4 * 4] =
                *(const float4*)(kbase + (size_t)(j0 + row) * DK + c4 * 4);
            *(float4*)&Vs[row * TSTRIDE + c4 * 4] =
                *(const float4*)(vbase + (size_t)(j0 + row) * DK + c4 * 4);
        }
        __syncthreads();

        // S = Q K^T (4x4 per thread)
        float s[4][4];
#pragma unroll
        for (int i = 0; i < 4; i++)
#pragma unroll
            for (int j = 0; j < 4; j++) s[i][j] = 0.f;

#pragma unroll
        for (int kk = 0; kk < 64; kk += 4) {
            float4 qv[4], kv[4];
#pragma unroll
            for (int i = 0; i < 4; i++) qv[i] = *(float4*)&Qs[(ty4 + i) * TSTRIDE + kk];
#pragma unroll
            for (int j = 0; j < 4; j++) kv[j] = *(float4*)&Ks[(tx4 + j) * TSTRIDE + kk];
#pragma unroll
            for (int i = 0; i < 4; i++)
#pragma unroll
                for (int j = 0; j < 4; j++) {
                    s[i][j] = fmaf(qv[i].x, kv[j].x, s[i][j]);
                    s[i][j] = fmaf(qv[i].y, kv[j].y, s[i][j]);
                    s[i][j] = fmaf(qv[i].z, kv[j].z, s[i][j]);
                    s[i][j] = fmaf(qv[i].w, kv[j].w, s[i][j]);
                }
        }

        const bool diag = (jt == qi);
#pragma unroll
        for (int i = 0; i < 4; i++)
#pragma unroll
            for (int j = 0; j < 4; j++) {
                s[i][j] *= 0.125f;   // 1/sqrt(64)
                if (diag && (j0 + tx4 + j > q0 + ty4 + i)) s[i][j] = -3.0e38f;
            }

        // online softmax update, row owned by 16 consecutive lanes
#pragma unroll
        for (int i = 0; i < 4; i++) {
            float mx = fmaxf(fmaxf(s[i][0], s[i][1]), fmaxf(s[i][2], s[i][3]));
#pragma unroll
            for (int off = 8; off >= 1; off >>= 1)
                mx = fmaxf(mx, __shfl_xor_sync(0xffffffffu, mx, off));
            float mnew = fmaxf(m_i[i], mx);
            float alpha = __expf(m_i[i] - mnew);
            float p0 = __expf(s[i][0] - mnew);
            float p1 = __expf(s[i][1] - mnew);
            float p2 = __expf(s[i][2] - mnew);
            float p3 = __expf(s[i][3] - mnew);
            float rs = (p0 + p1) + (p2 + p3);
#pragma unroll
            for (int off = 8; off >= 1; off >>= 1)
                rs += __shfl_xor_sync(0xffffffffu, rs, off);
            l_i[i] = l_i[i] * alpha + rs;
            m_i[i] = mnew;
#pragma unroll
            for (int c = 0; c < 4; c++) acc[i][c] *= alpha;
            *(float4*)&Ps[(ty4 + i) * TSTRIDE + tx4] = make_float4(p0, p1, p2, p3);
        }
        __syncthreads();

        // acc += P @ V
#pragma unroll 8
        for (int k = 0; k < 64; k++) {
            float4 vv = *(float4*)&Vs[k * TSTRIDE + tx4];
#pragma unroll
            for (int i = 0; i < 4; i++) {
                float pp = Ps[(ty4 + i) * TSTRIDE + k];
                acc[i][0] = fmaf(pp, vv.x, acc[i][0]);
                acc[i][1] = fmaf(pp, vv.y, acc[i][1]);
                acc[i][2] = fmaf(pp, vv.z, acc[i][2]);
                acc[i][3] = fmaf(pp, vv.w, acc[i][3]);
            }
        }
    }

    // write context in [B,T,D] layout for the output projection
    const int b = bh >> 4, h = bh & 15;
#pragma unroll
    for (int i = 0; i < 4; i++) {
        float inv = 1.0f / l_i[i];
        int t = q0 + ty4 + i;
        float4 o = make_float4(acc[i][0] * inv, acc[i][1] * inv,
                               acc[i][2] * inv, acc[i][3] * inv);
        *(float4*)&g_ctx[((size_t)(b * SEQ + t)) * DMODEL + h * DK + tx4] = o;
    }
}

// ---------------- launch ----------------------------------------------------
extern "C" void kernel_launch(void* const* d_in, const int* in_sizes, int n_in,
                              void* d_out, int out_size)
{
    const float* query = (const float*)d_in[0];
    const float* key_  = (const float*)d_in[1];
    const float* value = (const float*)d_in[2];
    // d_in[3] = mask (causal tril, applied analytically)
    const float* Wq = (const float*)d_in[4];
    const float* bq = (const float*)d_in[5];
    const float* Wk = (const float*)d_in[6];
    const float* bk = (const float*)d_in[7];
    const float* Wv = (const float*)d_in[8];
    const float* bv = (const float*)d_in[9];
    const float* Wo = (const float*)d_in[10];
    const float* bo = (const float*)d_in[11];
    float* out = (float*)d_out;

    const int smem_attn = 4 * 64 * TSTRIDE * (int)sizeof(float);  // 69632 B
    cudaFuncSetAttribute(flash_attn, cudaFuncAttributeMaxDynamicSharedMemorySize, smem_attn);

    dim3 gg(MROWS / GBM, DMODEL / GBN);   // 64 x 16
    gemm_xwt<<<gg, 256>>>(query, Wq, bq, nullptr, 0);
    gemm_xwt<<<gg, 256>>>(key_,  Wk, bk, nullptr, 1);
    gemm_xwt<<<gg, 256>>>(value, Wv, bv, nullptr, 2);

    flash_attn<<<dim3(SEQ / 64, BATCH * HEADS), 256, smem_attn>>>();

    gemm_xwt<<<gg, 256>>>(nullptr, Wo, bo, out, 3);
}